// round 4
// baseline (speedup 1.0000x reference)
#include <cuda_runtime.h>
#include <cuda_bf16.h>
#include <cstdint>

#define D3 384
#define MT 2047          // nodes per tree
#define NT 32
#define NN 65504         // 32 * 2047
#define NINT 32736       // 32 * 1023 internal nodes

// ------------------------- device scratch ----------------------------------
__device__ float g_wxiou[NN * D3];      // W_iou*x + b_iou, all nodes
__device__ float g_wxf[NN * 128];       // W_f*x + b_f, internal nodes
__device__ float g_c[NN * 128];         // cell state

__device__ __align__(16) __nv_bfloat16 g_Wiou_h[D3 * 128];
__device__ __align__(16) __nv_bfloat16 g_Wiou_l[D3 * 128];
__device__ __align__(16) __nv_bfloat16 g_Uiou_h[D3 * 128];
__device__ __align__(16) __nv_bfloat16 g_Uiou_l[D3 * 128];
__device__ __align__(16) __nv_bfloat16 g_Wf_h[128 * 128];
__device__ __align__(16) __nv_bfloat16 g_Wf_l[128 * 128];
__device__ __align__(16) __nv_bfloat16 g_Uf_h[128 * 128];
__device__ __align__(16) __nv_bfloat16 g_Uf_l[128 * 128];

__device__ __forceinline__ float sigf(float x) {
    return 1.0f / (1.0f + __expf(-x));
}
__device__ __forceinline__ float tanhfast(float x) {
    return 1.0f - 2.0f / (__expf(2.0f * x) + 1.0f);
}

// ------------------------- mma / ldmatrix helpers ---------------------------
__device__ __forceinline__ void ldsm4(uint32_t addr, uint32_t* r) {
    asm volatile("ldmatrix.sync.aligned.m8n8.x4.shared.b16 {%0,%1,%2,%3}, [%4];"
                 : "=r"(r[0]), "=r"(r[1]), "=r"(r[2]), "=r"(r[3]) : "r"(addr));
}
__device__ __forceinline__ void mma16816(float* c, const uint32_t* a,
                                         uint32_t b0, uint32_t b1) {
    asm volatile(
        "mma.sync.aligned.m16n8k16.row.col.f32.bf16.bf16.f32 "
        "{%0,%1,%2,%3}, {%4,%5,%6,%7}, {%8,%9}, {%0,%1,%2,%3};"
        : "+f"(c[0]), "+f"(c[1]), "+f"(c[2]), "+f"(c[3])
        : "r"(a[0]), "r"(a[1]), "r"(a[2]), "r"(a[3]), "r"(b0), "r"(b1));
}
__device__ __forceinline__ void split1(float v, __nv_bfloat16& h, __nv_bfloat16& l) {
    h = __float2bfloat16(v);
    l = __float2bfloat16(v - __bfloat162float(h));
}
__device__ __forceinline__ void split_store4(float4 v, __nv_bfloat16* dh,
                                             __nv_bfloat16* dl) {
    __nv_bfloat16 h0, h1, h2, h3, l0, l1, l2, l3;
    split1(v.x, h0, l0); split1(v.y, h1, l1);
    split1(v.z, h2, l2); split1(v.w, h3, l3);
    __nv_bfloat162 p;
    p.x = h0; p.y = h1; ((__nv_bfloat162*)dh)[0] = p;
    p.x = h2; p.y = h3; ((__nv_bfloat162*)dh)[1] = p;
    p.x = l0; p.y = l1; ((__nv_bfloat162*)dl)[0] = p;
    p.x = l2; p.y = l3; ((__nv_bfloat162*)dl)[1] = p;
}

// ------------------------- weight split kernel ------------------------------
__global__ void k_cvt(const float* __restrict__ Wiou, const float* __restrict__ Uiou,
                      const float* __restrict__ Wf, const float* __restrict__ Uf)
{
    int idx = blockIdx.x * 256 + threadIdx.x;     // 384*128
    int n = idx >> 7, k = idx & 127;
    split1(Wiou[k * D3 + n], g_Wiou_h[n * 128 + k], g_Wiou_l[n * 128 + k]);
    split1(Uiou[k * D3 + n], g_Uiou_h[n * 128 + k], g_Uiou_l[n * 128 + k]);
    if (n < 128) {
        split1(Wf[k * 128 + n], g_Wf_h[n * 128 + k], g_Wf_l[n * 128 + k]);
        split1(Uf[k * 128 + n], g_Uf_h[n * 128 + k], g_Uf_l[n * 128 + k]);
    }
}

// ------------------------- precompute GEMMs ---------------------------------
// MODE 0: wxiou = features @ Wiou + b      (M=NN rows, N=384)
// MODE 1: wxf   = features[int] @ Wf + b   (M=NINT,    N=128)
#define SA 136   // smem row stride in bf16 (272B) -> ldmatrix conflict-free
#define SMEM_BYTES (4 * 64 * SA * 2)

template<int MODE>
__global__ __launch_bounds__(128) void k_mm(const float* __restrict__ Asrc,
                                            const float* __restrict__ bias)
{
    extern __shared__ __nv_bfloat16 sm[];
    __nv_bfloat16* As_h = sm;
    __nv_bfloat16* As_l = sm + 64 * SA;
    __nv_bfloat16* Bs_h = sm + 2 * 64 * SA;

    const int tid = threadIdx.x;
    const int row0 = blockIdx.x * 64;
    const int nb = blockIdx.y;

    const __nv_bfloat16* Bh = (MODE == 0) ? g_Wiou_h : g_Wf_h;
    const __nv_bfloat16* Bl = (MODE == 0) ? g_Wiou_l : g_Wf_l;

    {
        const int n0 = nb * 64;
#pragma unroll
        for (int s = 0; s < 8; s++) {
            int j = tid + s * 128;
            int r = j >> 4, q = j & 15;
            *(uint4*)&Bs_h[r * SA + q * 8] = *(const uint4*)&Bh[(n0 + r) * 128 + q * 8];
            *(uint4*)&Bs_h[64 * SA + r * SA + q * 8] =
                *(const uint4*)&Bl[(n0 + r) * 128 + q * 8];
        }
    }

#pragma unroll
    for (int s = 0; s < 16; s++) {
        int j = tid + s * 128;
        int r = j >> 5, kq = j & 31;
        int L = row0 + r;
        float4 v;
        if (MODE == 0) {
            int g = (L < NN) ? L : NN - 1;
            v = *(const float4*)&Asrc[g * 128 + kq * 4];
        } else {
            int Lc = (L < NINT) ? L : NINT - 1;
            int t = Lc / 1023;
            int g = t * MT + (Lc - t * 1023);
            v = *(const float4*)&Asrc[g * 128 + kq * 4];
        }
        split_store4(v, &As_h[r * SA + kq * 4], &As_l[r * SA + kq * 4]);
    }
    __syncthreads();

    const int lane = tid & 31, wid = tid >> 5;
    const int wm = (wid & 1) * 32, wn = (wid >> 1) * 32;

    float acc[2][4][4];
#pragma unroll
    for (int i = 0; i < 2; i++)
#pragma unroll
        for (int j = 0; j < 4; j++)
#pragma unroll
            for (int k = 0; k < 4; k++) acc[i][j][k] = 0.0f;

    const uint32_t smbase = (uint32_t)__cvta_generic_to_shared(sm);
    const uint32_t offAl = 64 * SA * 2;
    const uint32_t offBh = 2 * 64 * SA * 2;
    const uint32_t offBl = 3 * 64 * SA * 2;

    const int rA = lane & 15;
    const int kA8 = (lane >> 4) * 8;
    uint32_t adA0 = smbase + ((wm + rA) * SA + kA8) * 2;
    uint32_t adA1 = smbase + ((wm + 16 + rA) * SA + kA8) * 2;
    const int rB = (lane & 7) + ((lane >> 4) * 8);
    const int kB8 = ((lane >> 3) & 1) * 8;
    uint32_t adB0 = smbase + offBh + ((wn + rB) * SA + kB8) * 2;
    uint32_t adB1 = smbase + offBh + ((wn + 16 + rB) * SA + kB8) * 2;

#pragma unroll
    for (int kc = 0; kc < 8; kc++) {
        const uint32_t ko = kc * 32;
        uint32_t a_h[2][4], a_l[2][4], b_h[2][4], b_l[2][4];
        ldsm4(adA0 + ko, a_h[0]);
        ldsm4(adA1 + ko, a_h[1]);
        ldsm4(adA0 + offAl + ko, a_l[0]);
        ldsm4(adA1 + offAl + ko, a_l[1]);
        ldsm4(adB0 + ko, b_h[0]);
        ldsm4(adB1 + ko, b_h[1]);
        ldsm4(adB0 + (offBl - offBh) + ko, b_l[0]);
        ldsm4(adB1 + (offBl - offBh) + ko, b_l[1]);
#pragma unroll
        for (int mi = 0; mi < 2; mi++)
#pragma unroll
            for (int nt = 0; nt < 4; nt++) {
                uint32_t bh0 = b_h[nt >> 1][(nt & 1) * 2];
                uint32_t bh1 = b_h[nt >> 1][(nt & 1) * 2 + 1];
                uint32_t bl0 = b_l[nt >> 1][(nt & 1) * 2];
                uint32_t bl1 = b_l[nt >> 1][(nt & 1) * 2 + 1];
                mma16816(acc[mi][nt], a_h[mi], bh0, bh1);
                mma16816(acc[mi][nt], a_l[mi], bh0, bh1);
                mma16816(acc[mi][nt], a_h[mi], bl0, bl1);
            }
    }

    const int er = lane >> 2;
    const int ec = (lane & 3) * 2;
#pragma unroll
    for (int mi = 0; mi < 2; mi++)
#pragma unroll
        for (int nt = 0; nt < 4; nt++) {
            int n = nb * 64 + wn + nt * 8 + ec;
#pragma unroll
            for (int half = 0; half < 2; half++) {
                int L = row0 + wm + mi * 16 + er + half * 8;
                float c0 = acc[mi][nt][half * 2 + 0];
                float c1 = acc[mi][nt][half * 2 + 1];
                if (MODE == 0) {
                    if (L < NN) {
                        float2 o;
                        o.x = c0 + bias[n];
                        o.y = c1 + bias[n + 1];
                        *(float2*)&g_wxiou[L * D3 + n] = o;
                    }
                } else {
                    if (L < NINT) {
                        int t = L / 1023;
                        int g = t * MT + (L - t * 1023);
                        float2 o;
                        o.x = c0 + bias[n];
                        o.y = c1 + bias[n + 1];
                        *(float2*)&g_wxf[g * 128 + n] = o;
                    }
                }
            }
        }
}

// ------------------------- leaf pass (vectorized) ---------------------------
__global__ void k_leaf(float* __restrict__ h)
{
    int idx = blockIdx.x * 256 + threadIdx.x;   // 32768 * 32 (float4 per thread)
    int lr = idx >> 5, c4 = (idx & 31) * 4;
    int t = lr >> 10, r = lr & 1023;
    int g = t * MT + 1023 + r;
    float4 wi = *(const float4*)&g_wxiou[g * D3 + c4];
    float4 wo = *(const float4*)&g_wxiou[g * D3 + 128 + c4];
    float4 wu = *(const float4*)&g_wxiou[g * D3 + 256 + c4];
    float4 cres, hres;
    {
        float cn = sigf(wi.x) * tanhfast(wu.x);
        cres.x = cn; hres.x = sigf(wo.x) * tanhfast(cn);
    }
    {
        float cn = sigf(wi.y) * tanhfast(wu.y);
        cres.y = cn; hres.y = sigf(wo.y) * tanhfast(cn);
    }
    {
        float cn = sigf(wi.z) * tanhfast(wu.z);
        cres.z = cn; hres.z = sigf(wo.z) * tanhfast(cn);
    }
    {
        float cn = sigf(wi.w) * tanhfast(wu.w);
        cres.w = cn; hres.w = sigf(wo.w) * tanhfast(cn);
    }
    *(float4*)&g_c[g * 128 + c4] = cres;
    *(float4*)&h[g * 128 + c4] = hres;
}

// ------------------------- fused level kernel -------------------------------
// One CTA: 64 contiguous child rows -> 32 parents. Phases:
//   (1) load child h, split bf16; build parent-sum A, split
//   (2) F-GEMM 64x128 over Uf (2 chunks of 64 cols), fc into smem
//   (3) IOU-GEMM 32x384 over Uiou (6 chunks), raw acc into smem
//   (4) combine -> write g_c, h for parents
#define FC_S 132
#define IOU_S 388
// bf16 region: As(2*64*SA) + Ap(2*32*SA) + Bs(2*64*SA)
#define LV_BF16 (2 * 64 * SA + 2 * 32 * SA + 2 * 64 * SA)
#define LV_SMEM (LV_BF16 * 2 + 64 * FC_S * 4 + 32 * IOU_S * 4)

__global__ __launch_bounds__(256) void k_level(float* __restrict__ h, int dd)
{
    extern __shared__ __nv_bfloat16 sm[];
    __nv_bfloat16* As_h = sm;                       // 64*SA
    __nv_bfloat16* As_l = sm + 64 * SA;
    __nv_bfloat16* Ap_h = sm + 2 * 64 * SA;         // 32*SA
    __nv_bfloat16* Ap_l = sm + 2 * 64 * SA + 32 * SA;
    __nv_bfloat16* Bs_h = sm + 2 * 64 * SA + 2 * 32 * SA;   // 64*SA
    __nv_bfloat16* Bs_l = Bs_h + 64 * SA;
    float* FCs  = (float*)(sm + LV_BF16);           // 64 x FC_S
    float* IOUs = FCs + 64 * FC_S;                  // 32 x IOU_S

    const int tid = threadIdx.x;
    const int lane = tid & 31, wid = tid >> 5;
    const int cs = dd + 1;
    const int CH = 1 << cs;
    const int L0 = blockIdx.x * 64;
    const int t = L0 >> cs;
    const int rr0 = L0 & (CH - 1);
    const int gc0 = t * MT + (CH - 1) + rr0;                 // first child
    const int gp0 = t * MT + ((CH >> 1) - 1) + (rr0 >> 1);   // first parent

    // ---- (1) load A tiles ----
#pragma unroll
    for (int s = 0; s < 8; s++) {
        int j = tid + s * 256;
        int r = j >> 5, kq = j & 31;
        float4 v = *(const float4*)&h[(gc0 + r) * 128 + kq * 4];
        split_store4(v, &As_h[r * SA + kq * 4], &As_l[r * SA + kq * 4]);
    }
#pragma unroll
    for (int s = 0; s < 4; s++) {
        int j = tid + s * 256;
        int r = j >> 5, kq = j & 31;
        float4 v1 = *(const float4*)&h[(gc0 + 2 * r) * 128 + kq * 4];
        float4 v2 = *(const float4*)&h[(gc0 + 2 * r + 1) * 128 + kq * 4];
        float4 v = make_float4(v1.x + v2.x, v1.y + v2.y, v1.z + v2.z, v1.w + v2.w);
        split_store4(v, &Ap_h[r * SA + kq * 4], &Ap_l[r * SA + kq * 4]);
    }

    const uint32_t smbase = (uint32_t)__cvta_generic_to_shared(sm);
    const uint32_t offAl  = 64 * SA * 2;
    const uint32_t offApH = 2 * 64 * SA * 2;
    const uint32_t offApL = offApH + 32 * SA * 2;
    const uint32_t offBh  = offApH + 2 * 32 * SA * 2;
    const uint32_t offBl  = offBh + 64 * SA * 2;

    const int rA  = lane & 15;
    const int kA8 = (lane >> 4) * 8;
    const int rB  = (lane & 7) + ((lane >> 4) * 8);
    const int kB8 = ((lane >> 3) & 1) * 8;
    const int er = lane >> 2;
    const int ec = (lane & 3) * 2;

    // ---- (2) F phase: N=128 in 2 chunks ----
    {
        const int wm = (wid & 1) * 32;
        const int wn = (wid >> 1) * 16;
        uint32_t adA0 = smbase + ((wm + rA) * SA + kA8) * 2;
        uint32_t adA1 = smbase + ((wm + 16 + rA) * SA + kA8) * 2;
        uint32_t adB  = smbase + offBh + ((wn + rB) * SA + kB8) * 2;

        for (int nb = 0; nb < 2; nb++) {
            __syncthreads();
#pragma unroll
            for (int s = 0; s < 4; s++) {
                int j = tid + s * 256;
                int r = j >> 4, q = j & 15;
                *(uint4*)&Bs_h[r * SA + q * 8] =
                    *(const uint4*)&g_Uf_h[(nb * 64 + r) * 128 + q * 8];
                *(uint4*)&Bs_l[r * SA + q * 8] =
                    *(const uint4*)&g_Uf_l[(nb * 64 + r) * 128 + q * 8];
            }
            __syncthreads();

            float acc[2][2][4];
#pragma unroll
            for (int i = 0; i < 2; i++)
#pragma unroll
                for (int j = 0; j < 2; j++)
#pragma unroll
                    for (int k = 0; k < 4; k++) acc[i][j][k] = 0.0f;

#pragma unroll
            for (int kc = 0; kc < 8; kc++) {
                const uint32_t ko = kc * 32;
                uint32_t a_h[2][4], a_l[2][4], b_h[4], b_l[4];
                ldsm4(adA0 + ko, a_h[0]);
                ldsm4(adA1 + ko, a_h[1]);
                ldsm4(adA0 + offAl + ko, a_l[0]);
                ldsm4(adA1 + offAl + ko, a_l[1]);
                ldsm4(adB + ko, b_h);
                ldsm4(adB + (offBl - offBh) + ko, b_l);
#pragma unroll
                for (int mi = 0; mi < 2; mi++)
#pragma unroll
                    for (int nf = 0; nf < 2; nf++) {
                        mma16816(acc[mi][nf], a_h[mi], b_h[nf * 2], b_h[nf * 2 + 1]);
                        mma16816(acc[mi][nf], a_l[mi], b_h[nf * 2], b_h[nf * 2 + 1]);
                        mma16816(acc[mi][nf], a_h[mi], b_l[nf * 2], b_l[nf * 2 + 1]);
                    }
            }
            // epilogue: fc = sig(acc + wxf[parent]) * c[child]
#pragma unroll
            for (int mi = 0; mi < 2; mi++)
#pragma unroll
                for (int nf = 0; nf < 2; nf++) {
                    int nn = nb * 64 + wn + nf * 8 + ec;
#pragma unroll
                    for (int half = 0; half < 2; half++) {
                        int lr = wm + mi * 16 + er + half * 8;
                        int gc = gc0 + lr;
                        int gp = gp0 + (lr >> 1);
                        float2 wf = *(const float2*)&g_wxf[gp * 128 + nn];
                        float2 cc = *(const float2*)&g_c[gc * 128 + nn];
                        float2 o;
                        o.x = sigf(acc[mi][nf][half * 2] + wf.x) * cc.x;
                        o.y = sigf(acc[mi][nf][half * 2 + 1] + wf.y) * cc.y;
                        *(float2*)&FCs[lr * FC_S + nn] = o;
                    }
                }
        }
    }

    // ---- (3) IOU phase: M=32 parents, N=384 in 6 chunks ----
    {
        const int wm = (wid & 1) * 16;
        const int wn = (wid >> 1) * 16;
        uint32_t adA = smbase + offApH + ((wm + rA) * SA + kA8) * 2;
        uint32_t adB = smbase + offBh + ((wn + rB) * SA + kB8) * 2;

        for (int nb = 0; nb < 6; nb++) {
            __syncthreads();
#pragma unroll
            for (int s = 0; s < 4; s++) {
                int j = tid + s * 256;
                int r = j >> 4, q = j & 15;
                *(uint4*)&Bs_h[r * SA + q * 8] =
                    *(const uint4*)&g_Uiou_h[(nb * 64 + r) * 128 + q * 8];
                *(uint4*)&Bs_l[r * SA + q * 8] =
                    *(const uint4*)&g_Uiou_l[(nb * 64 + r) * 128 + q * 8];
            }
            __syncthreads();

            float acc[2][4];
#pragma unroll
            for (int j = 0; j < 2; j++)
#pragma unroll
                for (int k = 0; k < 4; k++) acc[j][k] = 0.0f;

#pragma unroll
            for (int kc = 0; kc < 8; kc++) {
                const uint32_t ko = kc * 32;
                uint32_t a_h[4], a_l[4], b_h[4], b_l[4];
                ldsm4(adA + ko, a_h);
                ldsm4(adA + (offApL - offApH) + ko, a_l);
                ldsm4(adB + ko, b_h);
                ldsm4(adB + (offBl - offBh) + ko, b_l);
#pragma unroll
                for (int nf = 0; nf < 2; nf++) {
                    mma16816(acc[nf], a_h, b_h[nf * 2], b_h[nf * 2 + 1]);
                    mma16816(acc[nf], a_l, b_h[nf * 2], b_h[nf * 2 + 1]);
                    mma16816(acc[nf], a_h, b_l[nf * 2], b_l[nf * 2 + 1]);
                }
            }
#pragma unroll
            for (int nf = 0; nf < 2; nf++) {
                int nn = nb * 64 + wn + nf * 8 + ec;
#pragma unroll
                for (int half = 0; half < 2; half++) {
                    int pr = wm + er + half * 8;
                    float2 o;
                    o.x = acc[nf][half * 2];
                    o.y = acc[nf][half * 2 + 1];
                    *(float2*)&IOUs[pr * IOU_S + nn] = o;
                }
            }
        }
    }
    __syncthreads();

    // ---- (4) combine: 32 parents x 128 cols ----
#pragma unroll
    for (int s = 0; s < 4; s++) {
        int j = tid + s * 256;
        int pr = j >> 5, c4 = (j & 31) * 4;
        int gp = gp0 + pr;
        float4 ai = *(const float4*)&IOUs[pr * IOU_S + c4];
        float4 ao = *(const float4*)&IOUs[pr * IOU_S + 128 + c4];
        float4 au = *(const float4*)&IOUs[pr * IOU_S + 256 + c4];
        float4 wi = *(const float4*)&g_wxiou[gp * D3 + c4];
        float4 wo = *(const float4*)&g_wxiou[gp * D3 + 128 + c4];
        float4 wu = *(const float4*)&g_wxiou[gp * D3 + 256 + c4];
        float4 f1 = *(const float4*)&FCs[(2 * pr) * FC_S + c4];
        float4 f2 = *(const float4*)&FCs[(2 * pr + 1) * FC_S + c4];
        float4 cres, hres;
        {
            float cn = sigf(ai.x + wi.x) * tanhfast(au.x + wu.x) + f1.x + f2.x;
            cres.x = cn; hres.x = sigf(ao.x + wo.x) * tanhfast(cn);
        }
        {
            float cn = sigf(ai.y + wi.y) * tanhfast(au.y + wu.y) + f1.y + f2.y;
            cres.y = cn; hres.y = sigf(ao.y + wo.y) * tanhfast(cn);
        }
        {
            float cn = sigf(ai.z + wi.z) * tanhfast(au.z + wu.z) + f1.z + f2.z;
            cres.z = cn; hres.z = sigf(ao.z + wo.z) * tanhfast(cn);
        }
        {
            float cn = sigf(ai.w + wi.w) * tanhfast(au.w + wu.w) + f1.w + f2.w;
            cres.w = cn; hres.w = sigf(ao.w + wo.w) * tanhfast(cn);
        }
        *(float4*)&g_c[gp * 128 + c4] = cres;
        *(float4*)&h[gp * 128 + c4] = hres;
    }
}

// ------------------------- tail (levels 4..0), SIMT -------------------------
__global__ __launch_bounds__(256) void k_tail(
    float* __restrict__ h, const float* __restrict__ Uf,
    const float* __restrict__ Uiou)
{
    __shared__ __align__(16) float Hs[32 * 128];
    __shared__ __align__(16) float FC[32 * 128];
    const int tid = threadIdx.x;
    const int base = blockIdx.x * MT;

    for (int dd = 4; dd >= 0; dd--) {
        const int P = 1 << dd;
        const int Sp = P - 1;
        const int Sc = 2 * P - 1;
        const int CR = 2 * P;

        __syncthreads();
        for (int i = tid; i < CR * 128; i += 256)
            Hs[i] = h[(base + Sc + (i >> 7)) * 128 + (i & 127)];
        __syncthreads();

        for (int tt = tid; tt < CR * 32; tt += 256) {
            int r = tt >> 5;
            int col = (tt & 31) * 4;
            float4 acc = make_float4(0.f, 0.f, 0.f, 0.f);
#pragma unroll 4
            for (int k = 0; k < 128; k++) {
                float a = Hs[r * 128 + k];
                float4 b = *(const float4*)&Uf[k * 128 + col];
                acc.x += a * b.x; acc.y += a * b.y;
                acc.z += a * b.z; acc.w += a * b.w;
            }
            int gc = base + Sc + r;
            int gp = base + Sp + (r >> 1);
            float4 wf = *(const float4*)&g_wxf[gp * 128 + col];
            float4 cc = *(const float4*)&g_c[gc * 128 + col];
            float4 fc;
            fc.x = sigf(acc.x + wf.x) * cc.x;
            fc.y = sigf(acc.y + wf.y) * cc.y;
            fc.z = sigf(acc.z + wf.z) * cc.z;
            fc.w = sigf(acc.w + wf.w) * cc.w;
            *(float4*)&FC[r * 128 + col] = fc;
        }
        __syncthreads();

        for (int tt = tid; tt < P * 32; tt += 256) {
            int r = tt >> 5;
            int col = (tt & 31) * 4;
            float4 a0 = make_float4(0.f, 0.f, 0.f, 0.f);
            float4 a1 = a0, a2 = a0;
#pragma unroll 4
            for (int k = 0; k < 128; k++) {
                float a = Hs[(2 * r) * 128 + k] + Hs[(2 * r + 1) * 128 + k];
                float4 b0 = *(const float4*)&Uiou[k * D3 + col];
                float4 b1 = *(const float4*)&Uiou[k * D3 + 128 + col];
                float4 b2 = *(const float4*)&Uiou[k * D3 + 256 + col];
                a0.x += a * b0.x; a0.y += a * b0.y; a0.z += a * b0.z; a0.w += a * b0.w;
                a1.x += a * b1.x; a1.y += a * b1.y; a1.z += a * b1.z; a1.w += a * b1.w;
                a2.x += a * b2.x; a2.y += a * b2.y; a2.z += a * b2.z; a2.w += a * b2.w;
            }
            int gp = base + Sp + r;
            float4 w0 = *(const float4*)&g_wxiou[gp * D3 + col];
            float4 w1 = *(const float4*)&g_wxiou[gp * D3 + 128 + col];
            float4 w2 = *(const float4*)&g_wxiou[gp * D3 + 256 + col];
            float4 f1 = *(const float4*)&FC[(2 * r) * 128 + col];
            float4 f2 = *(const float4*)&FC[(2 * r + 1) * 128 + col];
            float4 cres, hres;
            {
                float cn = sigf(a0.x + w0.x) * tanhfast(a2.x + w2.x) + f1.x + f2.x;
                cres.x = cn; hres.x = sigf(a1.x + w1.x) * tanhfast(cn);
            }
            {
                float cn = sigf(a0.y + w0.y) * tanhfast(a2.y + w2.y) + f1.y + f2.y;
                cres.y = cn; hres.y = sigf(a1.y + w1.y) * tanhfast(cn);
            }
            {
                float cn = sigf(a0.z + w0.z) * tanhfast(a2.z + w2.z) + f1.z + f2.z;
                cres.z = cn; hres.z = sigf(a1.z + w1.z) * tanhfast(cn);
            }
            {
                float cn = sigf(a0.w + w0.w) * tanhfast(a2.w + w2.w) + f1.w + f2.w;
                cres.w = cn; hres.w = sigf(a1.w + w1.w) * tanhfast(cn);
            }
            *(float4*)&g_c[gp * 128 + col] = cres;
            *(float4*)&h[gp * 128 + col] = hres;
        }
        __syncthreads();
    }
}

// ---------------------------------------------------------------------------
extern "C" void kernel_launch(void* const* d_in, const int* in_sizes, int n_in,
                              void* d_out, int out_size)
{
    const float* features = (const float*)d_in[0];
    const float* W_iou    = (const float*)d_in[1];
    const float* b_iou    = (const float*)d_in[2];
    const float* U_iou    = (const float*)d_in[3];
    const float* W_f      = (const float*)d_in[4];
    const float* b_f      = (const float*)d_in[5];
    const float* U_f      = (const float*)d_in[6];
    float* h = (float*)d_out;

    cudaFuncSetAttribute(k_mm<0>, cudaFuncAttributeMaxDynamicSharedMemorySize, SMEM_BYTES);
    cudaFuncSetAttribute(k_mm<1>, cudaFuncAttributeMaxDynamicSharedMemorySize, SMEM_BYTES);
    cudaFuncSetAttribute(k_level, cudaFuncAttributeMaxDynamicSharedMemorySize, LV_SMEM);

    // Split weights to bf16 hi/lo, transposed
    k_cvt<<<192, 256>>>(W_iou, U_iou, W_f, U_f);

    // Level-independent GEMMs
    k_mm<0><<<dim3(1024, 6), 128, SMEM_BYTES>>>(features, b_iou);
    k_mm<1><<<dim3(512, 2), 128, SMEM_BYTES>>>(features, b_f);

    // Leaves (vectorized)
    k_leaf<<<4096, 256>>>(h);

    // Fused levels: parents at depth dd = 9..5 (children = NT << (dd+1))
    for (int dd = 9; dd >= 5; dd--)
        k_level<<<(NT << (dd + 1)) / 64, 256, LV_SMEM>>>(h, dd);

    // Tail: levels 4..0
    k_tail<<<32, 256>>>(h, U_f, U_iou);
}

// round 6
// speedup vs baseline: 1.0683x; 1.0683x over previous
#include <cuda_runtime.h>
#include <cuda_bf16.h>
#include <cstdint>

#define D3 384
#define MT 2047          // nodes per tree
#define NT 32
#define NN 65504         // 32 * 2047
#define NINT 32736       // 32 * 1023 internal nodes
#define SA 136           // smem row stride in bf16 (272B) -> ldmatrix conflict-free

// ------------------------- device scratch ----------------------------------
__device__ float g_wxiou[NN * D3];      // W_iou*x + b_iou, all nodes
__device__ float g_wxf[NN * 128];       // W_f*x + b_f, internal nodes
__device__ float g_c[NN * 128];         // cell state
__device__ float g_fc[NN * 128];        // f(child)*c(child)

__device__ __align__(16) __nv_bfloat16 g_Wiou_h[D3 * 128];
__device__ __align__(16) __nv_bfloat16 g_Wiou_l[D3 * 128];
__device__ __align__(16) __nv_bfloat16 g_Uiou_h[D3 * 128];
__device__ __align__(16) __nv_bfloat16 g_Uiou_l[D3 * 128];
__device__ __align__(16) __nv_bfloat16 g_Wf_h[128 * 128];
__device__ __align__(16) __nv_bfloat16 g_Wf_l[128 * 128];
__device__ __align__(16) __nv_bfloat16 g_Uf_h[128 * 128];
__device__ __align__(16) __nv_bfloat16 g_Uf_l[128 * 128];

__device__ __forceinline__ float sigf(float x) {
    return 1.0f / (1.0f + __expf(-x));
}
__device__ __forceinline__ float tanhfast(float x) {
    return 1.0f - 2.0f / (__expf(2.0f * x) + 1.0f);
}

// ------------------------- mma / ldmatrix helpers ---------------------------
__device__ __forceinline__ void ldsm4(uint32_t addr, uint32_t* r) {
    asm volatile("ldmatrix.sync.aligned.m8n8.x4.shared.b16 {%0,%1,%2,%3}, [%4];"
                 : "=r"(r[0]), "=r"(r[1]), "=r"(r[2]), "=r"(r[3]) : "r"(addr));
}
__device__ __forceinline__ void mma16816(float* c, const uint32_t* a,
                                         uint32_t b0, uint32_t b1) {
    asm volatile(
        "mma.sync.aligned.m16n8k16.row.col.f32.bf16.bf16.f32 "
        "{%0,%1,%2,%3}, {%4,%5,%6,%7}, {%8,%9}, {%0,%1,%2,%3};"
        : "+f"(c[0]), "+f"(c[1]), "+f"(c[2]), "+f"(c[3])
        : "r"(a[0]), "r"(a[1]), "r"(a[2]), "r"(a[3]), "r"(b0), "r"(b1));
}
__device__ __forceinline__ void split1(float v, __nv_bfloat16& h, __nv_bfloat16& l) {
    h = __float2bfloat16(v);
    l = __float2bfloat16(v - __bfloat162float(h));
}
__device__ __forceinline__ void split_store4(float4 v, __nv_bfloat16* dh,
                                             __nv_bfloat16* dl) {
    __nv_bfloat16 h0, h1, h2, h3, l0, l1, l2, l3;
    split1(v.x, h0, l0); split1(v.y, h1, l1);
    split1(v.z, h2, l2); split1(v.w, h3, l3);
    __nv_bfloat162 p;
    p.x = h0; p.y = h1; ((__nv_bfloat162*)dh)[0] = p;
    p.x = h2; p.y = h3; ((__nv_bfloat162*)dh)[1] = p;
    p.x = l0; p.y = l1; ((__nv_bfloat162*)dl)[0] = p;
    p.x = l2; p.y = l3; ((__nv_bfloat162*)dl)[1] = p;
}

// ------------------------- weight split kernel ------------------------------
__global__ void k_cvt(const float* __restrict__ Wiou, const float* __restrict__ Uiou,
                      const float* __restrict__ Wf, const float* __restrict__ Uf)
{
    int idx = blockIdx.x * 256 + threadIdx.x;     // 384*128
    int n = idx >> 7, k = idx & 127;
    split1(Wiou[k * D3 + n], g_Wiou_h[n * 128 + k], g_Wiou_l[n * 128 + k]);
    split1(Uiou[k * D3 + n], g_Uiou_h[n * 128 + k], g_Uiou_l[n * 128 + k]);
    if (n < 128) {
        split1(Wf[k * 128 + n], g_Wf_h[n * 128 + k], g_Wf_l[n * 128 + k]);
        split1(Uf[k * 128 + n], g_Uf_h[n * 128 + k], g_Uf_l[n * 128 + k]);
    }
}

// ------------------------- wxiou precompute GEMM ----------------------------
// wxiou = features @ Wiou + b  (M=NN, N=384 in 6 y-blocks, BM=64)
#define MM_SMEM (4 * 64 * SA * 2)
__global__ __launch_bounds__(128) void k_wxiou(const float* __restrict__ Asrc,
                                               const float* __restrict__ bias)
{
    extern __shared__ __nv_bfloat16 sm[];
    __nv_bfloat16* As_h = sm;
    __nv_bfloat16* As_l = sm + 64 * SA;
    __nv_bfloat16* Bs_h = sm + 2 * 64 * SA;

    const int tid = threadIdx.x;
    const int row0 = blockIdx.x * 64;
    const int nb = blockIdx.y;

    {
        const int n0 = nb * 64;
#pragma unroll
        for (int s = 0; s < 8; s++) {
            int j = tid + s * 128;
            int r = j >> 4, q = j & 15;
            *(uint4*)&Bs_h[r * SA + q * 8] =
                *(const uint4*)&g_Wiou_h[(n0 + r) * 128 + q * 8];
            *(uint4*)&Bs_h[64 * SA + r * SA + q * 8] =
                *(const uint4*)&g_Wiou_l[(n0 + r) * 128 + q * 8];
        }
    }
#pragma unroll
    for (int s = 0; s < 16; s++) {
        int j = tid + s * 128;
        int r = j >> 5, kq = j & 31;
        int L = row0 + r;
        int g = (L < NN) ? L : NN - 1;
        float4 v = *(const float4*)&Asrc[g * 128 + kq * 4];
        split_store4(v, &As_h[r * SA + kq * 4], &As_l[r * SA + kq * 4]);
    }
    __syncthreads();

    const int lane = tid & 31, wid = tid >> 5;
    const int wm = (wid & 1) * 32, wn = (wid >> 1) * 32;

    float acc[2][4][4];
#pragma unroll
    for (int i = 0; i < 2; i++)
#pragma unroll
        for (int j = 0; j < 4; j++)
#pragma unroll
            for (int k = 0; k < 4; k++) acc[i][j][k] = 0.0f;

    const uint32_t smbase = (uint32_t)__cvta_generic_to_shared(sm);
    const uint32_t offAl = 64 * SA * 2;
    const uint32_t offBh = 2 * 64 * SA * 2;
    const uint32_t offBl = 3 * 64 * SA * 2;

    const int rA = lane & 15;
    const int kA8 = (lane >> 4) * 8;
    uint32_t adA0 = smbase + ((wm + rA) * SA + kA8) * 2;
    uint32_t adA1 = smbase + ((wm + 16 + rA) * SA + kA8) * 2;
    const int rB = (lane & 7) + ((lane >> 4) * 8);
    const int kB8 = ((lane >> 3) & 1) * 8;
    uint32_t adB0 = smbase + offBh + ((wn + rB) * SA + kB8) * 2;
    uint32_t adB1 = smbase + offBh + ((wn + 16 + rB) * SA + kB8) * 2;

#pragma unroll
    for (int kc = 0; kc < 8; kc++) {
        const uint32_t ko = kc * 32;
        uint32_t a_h[2][4], a_l[2][4], b_h[2][4], b_l[2][4];
        ldsm4(adA0 + ko, a_h[0]);
        ldsm4(adA1 + ko, a_h[1]);
        ldsm4(adA0 + offAl + ko, a_l[0]);
        ldsm4(adA1 + offAl + ko, a_l[1]);
        ldsm4(adB0 + ko, b_h[0]);
        ldsm4(adB1 + ko, b_h[1]);
        ldsm4(adB0 + (offBl - offBh) + ko, b_l[0]);
        ldsm4(adB1 + (offBl - offBh) + ko, b_l[1]);
#pragma unroll
        for (int mi = 0; mi < 2; mi++)
#pragma unroll
            for (int nt = 0; nt < 4; nt++) {
                uint32_t bh0 = b_h[nt >> 1][(nt & 1) * 2];
                uint32_t bh1 = b_h[nt >> 1][(nt & 1) * 2 + 1];
                uint32_t bl0 = b_l[nt >> 1][(nt & 1) * 2];
                uint32_t bl1 = b_l[nt >> 1][(nt & 1) * 2 + 1];
                mma16816(acc[mi][nt], a_h[mi], bh0, bh1);
                mma16816(acc[mi][nt], a_l[mi], bh0, bh1);
                mma16816(acc[mi][nt], a_h[mi], bl0, bl1);
            }
    }

    const int er = lane >> 2;
    const int ec = (lane & 3) * 2;
#pragma unroll
    for (int mi = 0; mi < 2; mi++)
#pragma unroll
        for (int nt = 0; nt < 4; nt++) {
            int n = nb * 64 + wn + nt * 8 + ec;
#pragma unroll
            for (int half = 0; half < 2; half++) {
                int L = row0 + wm + mi * 16 + er + half * 8;
                if (L < NN) {
                    float2 o;
                    o.x = acc[mi][nt][half * 2 + 0] + bias[n];
                    o.y = acc[mi][nt][half * 2 + 1] + bias[n + 1];
                    *(float2*)&g_wxiou[L * D3 + n] = o;
                }
            }
        }
}

// ------------------------- full-N 128-col GEMM ------------------------------
// MODE 0 (wxf):  A = features[internal], out = wxf + b_f   -> g_wxf
// MODE 1 (flvl): A = h[children],        out = sig(acc+wxf[par])*c -> g_fc
// BM=64, N=128 resident, 256 threads (8 warps, 2m x 4n), one sync.
#define G128_SMEM ((2 * 64 + 2 * 128) * SA * 2)
template<int MODE>
__global__ __launch_bounds__(256) void k_g128(const float* __restrict__ Asrc,
                                              const float* __restrict__ bias,
                                              int cs)
{
    extern __shared__ __nv_bfloat16 sm[];
    __nv_bfloat16* As_h = sm;
    __nv_bfloat16* As_l = sm + 64 * SA;
    __nv_bfloat16* Bs_h = sm + 2 * 64 * SA;
    __nv_bfloat16* Bs_l = sm + (2 * 64 + 128) * SA;

    const int tid = threadIdx.x;
    const int L0 = blockIdx.x * 64;

    int gc0 = 0, gp0 = 0;
    if (MODE == 1) {
        const int CH = 1 << cs;
        int t = L0 >> cs;
        int rr0 = L0 & (CH - 1);
        gc0 = t * MT + (CH - 1) + rr0;
        gp0 = t * MT + ((CH >> 1) - 1) + (rr0 >> 1);
    }

    // B: 128 rows x 128 k, hi+lo
    const __nv_bfloat16* Bh = (MODE == 0) ? g_Wf_h : g_Uf_h;
    const __nv_bfloat16* Bl = (MODE == 0) ? g_Wf_l : g_Uf_l;
#pragma unroll
    for (int s = 0; s < 8; s++) {
        int j = tid + s * 256;
        int r = j >> 4, q = j & 15;
        *(uint4*)&Bs_h[r * SA + q * 8] = *(const uint4*)&Bh[r * 128 + q * 8];
        *(uint4*)&Bs_l[r * SA + q * 8] = *(const uint4*)&Bl[r * 128 + q * 8];
    }
    // A: 64 rows x 128 k, fp32 -> split
#pragma unroll
    for (int s = 0; s < 8; s++) {
        int j = tid + s * 256;
        int r = j >> 5, kq = j & 31;
        float4 v;
        if (MODE == 0) {
            int L = L0 + r;
            int Lc = (L < NINT) ? L : NINT - 1;
            int t = Lc / 1023;
            int g = t * MT + (Lc - t * 1023);
            v = *(const float4*)&Asrc[g * 128 + kq * 4];
        } else {
            v = *(const float4*)&Asrc[(gc0 + r) * 128 + kq * 4];
        }
        split_store4(v, &As_h[r * SA + kq * 4], &As_l[r * SA + kq * 4]);
    }
    __syncthreads();

    const int lane = tid & 31, wid = tid >> 5;
    const int wm = (wid & 1) * 32, wn = (wid >> 1) * 32;

    float acc[2][4][4];
#pragma unroll
    for (int i = 0; i < 2; i++)
#pragma unroll
        for (int j = 0; j < 4; j++)
#pragma unroll
            for (int k = 0; k < 4; k++) acc[i][j][k] = 0.0f;

    const uint32_t smbase = (uint32_t)__cvta_generic_to_shared(sm);
    const uint32_t offAl = 64 * SA * 2;
    const uint32_t offBh = 2 * 64 * SA * 2;
    const uint32_t offBl = (2 * 64 + 128) * SA * 2;

    const int rA = lane & 15;
    const int kA8 = (lane >> 4) * 8;
    uint32_t adA0 = smbase + ((wm + rA) * SA + kA8) * 2;
    uint32_t adA1 = smbase + ((wm + 16 + rA) * SA + kA8) * 2;
    const int rB = (lane & 7) + ((lane >> 4) * 8);
    const int kB8 = ((lane >> 3) & 1) * 8;
    uint32_t adB0 = smbase + offBh + ((wn + rB) * SA + kB8) * 2;
    uint32_t adB1 = smbase + offBh + ((wn + 16 + rB) * SA + kB8) * 2;

#pragma unroll
    for (int kc = 0; kc < 8; kc++) {
        const uint32_t ko = kc * 32;
        uint32_t a_h[2][4], a_l[2][4], b_h[2][4], b_l[2][4];
        ldsm4(adA0 + ko, a_h[0]);
        ldsm4(adA1 + ko, a_h[1]);
        ldsm4(adA0 + offAl + ko, a_l[0]);
        ldsm4(adA1 + offAl + ko, a_l[1]);
        ldsm4(adB0 + ko, b_h[0]);
        ldsm4(adB1 + ko, b_h[1]);
        ldsm4(adB0 + (offBl - offBh) + ko, b_l[0]);
        ldsm4(adB1 + (offBl - offBh) + ko, b_l[1]);
#pragma unroll
        for (int mi = 0; mi < 2; mi++)
#pragma unroll
            for (int nt = 0; nt < 4; nt++) {
                uint32_t bh0 = b_h[nt >> 1][(nt & 1) * 2];
                uint32_t bh1 = b_h[nt >> 1][(nt & 1) * 2 + 1];
                uint32_t bl0 = b_l[nt >> 1][(nt & 1) * 2];
                uint32_t bl1 = b_l[nt >> 1][(nt & 1) * 2 + 1];
                mma16816(acc[mi][nt], a_h[mi], bh0, bh1);
                mma16816(acc[mi][nt], a_l[mi], bh0, bh1);
                mma16816(acc[mi][nt], a_h[mi], bl0, bl1);
            }
    }

    const int er = lane >> 2;
    const int ec = (lane & 3) * 2;
#pragma unroll
    for (int mi = 0; mi < 2; mi++)
#pragma unroll
        for (int nt = 0; nt < 4; nt++) {
            int n = wn + nt * 8 + ec;
#pragma unroll
            for (int half = 0; half < 2; half++) {
                int lr = wm + mi * 16 + er + half * 8;
                float c0 = acc[mi][nt][half * 2 + 0];
                float c1 = acc[mi][nt][half * 2 + 1];
                if (MODE == 0) {
                    int L = L0 + lr;
                    if (L < NINT) {
                        int t = L / 1023;
                        int g = t * MT + (L - t * 1023);
                        float2 o;
                        o.x = c0 + bias[n];
                        o.y = c1 + bias[n + 1];
                        *(float2*)&g_wxf[g * 128 + n] = o;
                    }
                } else {
                    int gc = gc0 + lr;
                    int gp = gp0 + (lr >> 1);
                    float2 wf = *(const float2*)&g_wxf[gp * 128 + n];
                    float2 cc = *(const float2*)&g_c[gc * 128 + n];
                    float2 o;
                    o.x = sigf(c0 + wf.x) * cc.x;
                    o.y = sigf(c1 + wf.y) * cc.y;
                    *(float2*)&g_fc[gc * 128 + n] = o;
                }
            }
        }
}

// ------------------------- IOU level kernel (full N=384) --------------------
// BM=32 parents, all 384 cols resident. Each thread owns (row,col) for i,o,u
// -> full cell update in epilogue. 256 threads (8 warps, 2m x 4n).
#define IOU_SMEM ((2 * 32 + 2 * 384) * SA * 2)   // 226,304 B
__global__ __launch_bounds__(256) void k_iou(float* __restrict__ h, int dd)
{
    extern __shared__ __nv_bfloat16 sm[];
    __nv_bfloat16* Ap_h = sm;                   // 32*SA
    __nv_bfloat16* Ap_l = sm + 32 * SA;
    __nv_bfloat16* Bs_h = sm + 2 * 32 * SA;     // 384*SA
    __nv_bfloat16* Bs_l = sm + (2 * 32 + 384) * SA;

    const int tid = threadIdx.x;
    const int P = 1 << dd;
    const int L0 = blockIdx.x * 32;
    const int t = L0 >> dd;
    const int rr0 = L0 & (P - 1);
    const int gp0 = t * MT + (P - 1) + rr0;
    const int gc0 = t * MT + (2 * P - 1) + 2 * rr0;

    // B: 384 rows x 128 k, hi+lo (6144 uint4 each)
    for (int j = tid; j < 6144; j += 256) {
        int r = j >> 4, q = j & 15;
        *(uint4*)&Bs_h[r * SA + q * 8] = *(const uint4*)&g_Uiou_h[r * 128 + q * 8];
        *(uint4*)&Bs_l[r * SA + q * 8] = *(const uint4*)&g_Uiou_l[r * 128 + q * 8];
    }
    // A: 32 pair-sum rows
#pragma unroll
    for (int s = 0; s < 4; s++) {
        int j = tid + s * 256;
        int r = j >> 5, kq = j & 31;
        float4 v1 = *(const float4*)&h[(gc0 + 2 * r) * 128 + kq * 4];
        float4 v2 = *(const float4*)&h[(gc0 + 2 * r + 1) * 128 + kq * 4];
        float4 v = make_float4(v1.x + v2.x, v1.y + v2.y, v1.z + v2.z, v1.w + v2.w);
        split_store4(v, &Ap_h[r * SA + kq * 4], &Ap_l[r * SA + kq * 4]);
    }
    __syncthreads();

    const int lane = tid & 31, wid = tid >> 5;
    const int wm = (wid & 1) * 16;       // 2 m-groups of 16 rows
    const int wn = (wid >> 1) * 32;      // 4 n-groups of 32 cols (within a set)

    float acc[3][4][4];
#pragma unroll
    for (int s = 0; s < 3; s++)
#pragma unroll
        for (int j = 0; j < 4; j++)
#pragma unroll
            for (int k = 0; k < 4; k++) acc[s][j][k] = 0.0f;

    const uint32_t smbase = (uint32_t)__cvta_generic_to_shared(sm);
    const uint32_t offAl = 32 * SA * 2;
    const uint32_t offBh = 2 * 32 * SA * 2;
    const uint32_t offBl = (2 * 32 + 384) * SA * 2;

    const int rA = lane & 15;
    const int kA8 = (lane >> 4) * 8;
    uint32_t adA = smbase + ((wm + rA) * SA + kA8) * 2;
    const int rB = (lane & 7) + ((lane >> 4) * 8);
    const int kB8 = ((lane >> 3) & 1) * 8;

    uint32_t adB[3][2];
#pragma unroll
    for (int s = 0; s < 3; s++) {
        adB[s][0] = smbase + offBh + ((s * 128 + wn + rB) * SA + kB8) * 2;
        adB[s][1] = smbase + offBh + ((s * 128 + wn + 16 + rB) * SA + kB8) * 2;
    }

#pragma unroll
    for (int kc = 0; kc < 8; kc++) {
        const uint32_t ko = kc * 32;
        uint32_t a_h[4], a_l[4];
        ldsm4(adA + ko, a_h);
        ldsm4(adA + offAl + ko, a_l);
#pragma unroll
        for (int s = 0; s < 3; s++) {
            uint32_t b_h[2][4], b_l[2][4];
            ldsm4(adB[s][0] + ko, b_h[0]);
            ldsm4(adB[s][1] + ko, b_h[1]);
            ldsm4(adB[s][0] + (offBl - offBh) + ko, b_l[0]);
            ldsm4(adB[s][1] + (offBl - offBh) + ko, b_l[1]);
#pragma unroll
            for (int nt = 0; nt < 4; nt++) {
                uint32_t bh0 = b_h[nt >> 1][(nt & 1) * 2];
                uint32_t bh1 = b_h[nt >> 1][(nt & 1) * 2 + 1];
                uint32_t bl0 = b_l[nt >> 1][(nt & 1) * 2];
                uint32_t bl1 = b_l[nt >> 1][(nt & 1) * 2 + 1];
                mma16816(acc[s][nt], a_h, bh0, bh1);
                mma16816(acc[s][nt], a_l, bh0, bh1);
                mma16816(acc[s][nt], a_h, bl0, bl1);
            }
        }
    }

    // epilogue: full cell update in registers
    const int er = lane >> 2;
    const int ec = (lane & 3) * 2;
#pragma unroll
    for (int nt = 0; nt < 4; nt++) {
        int col = wn + nt * 8 + ec;
#pragma unroll
        for (int half = 0; half < 2; half++) {
            int pr = wm + er + half * 8;
            int gp = gp0 + pr;
            int gc1 = gc0 + 2 * pr;
            float2 wi = *(const float2*)&g_wxiou[gp * D3 + col];
            float2 wo = *(const float2*)&g_wxiou[gp * D3 + 128 + col];
            float2 wu = *(const float2*)&g_wxiou[gp * D3 + 256 + col];
            float2 f1 = *(const float2*)&g_fc[gc1 * 128 + col];
            float2 f2 = *(const float2*)&g_fc[(gc1 + 1) * 128 + col];
            float2 cres, hres;
            {
                float cn = sigf(acc[0][nt][half * 2] + wi.x)
                         * tanhfast(acc[2][nt][half * 2] + wu.x) + f1.x + f2.x;
                cres.x = cn;
                hres.x = sigf(acc[1][nt][half * 2] + wo.x) * tanhfast(cn);
            }
            {
                float cn = sigf(acc[0][nt][half * 2 + 1] + wi.y)
                         * tanhfast(acc[2][nt][half * 2 + 1] + wu.y) + f1.y + f2.y;
                cres.y = cn;
                hres.y = sigf(acc[1][nt][half * 2 + 1] + wo.y) * tanhfast(cn);
            }
            *(float2*)&g_c[gp * 128 + col] = cres;
            *(float2*)&h[gp * 128 + col] = hres;
        }
    }
}

// ------------------------- leaf pass (vectorized) ---------------------------
__global__ void k_leaf(float* __restrict__ h)
{
    int idx = blockIdx.x * 256 + threadIdx.x;   // 32768 * 32 (float4 per thread)
    int lr = idx >> 5, c4 = (idx & 31) * 4;
    int t = lr >> 10, r = lr & 1023;
    int g = t * MT + 1023 + r;
    float4 wi = *(const float4*)&g_wxiou[g * D3 + c4];
    float4 wo = *(const float4*)&g_wxiou[g * D3 + 128 + c4];
    float4 wu = *(const float4*)&g_wxiou[g * D3 + 256 + c4];
    float4 cres, hres;
    {
        float cn = sigf(wi.x) * tanhfast(wu.x);
        cres.x = cn; hres.x = sigf(wo.x) * tanhfast(cn);
    }
    {
        float cn = sigf(wi.y) * tanhfast(wu.y);
        cres.y = cn; hres.y = sigf(wo.y) * tanhfast(cn);
    }
    {
        float cn = sigf(wi.z) * tanhfast(wu.z);
        cres.z = cn; hres.z = sigf(wo.z) * tanhfast(cn);
    }
    {
        float cn = sigf(wi.w) * tanhfast(wu.w);
        cres.w = cn; hres.w = sigf(wo.w) * tanhfast(cn);
    }
    *(float4*)&g_c[g * 128 + c4] = cres;
    *(float4*)&h[g * 128 + c4] = hres;
}

// ------------------------- tail (levels 4..0), SIMT -------------------------
__global__ __launch_bounds__(256) void k_tail(
    float* __restrict__ h, const float* __restrict__ Uf,
    const float* __restrict__ Uiou)
{
    __shared__ __align__(16) float Hs[32 * 128];
    __shared__ __align__(16) float FC[32 * 128];
    const int tid = threadIdx.x;
    const int base = blockIdx.x * MT;

    for (int dd = 4; dd >= 0; dd--) {
        const int P = 1 << dd;
        const int Sp = P - 1;
        const int Sc = 2 * P - 1;
        const int CR = 2 * P;

        __syncthreads();
        for (int i = tid; i < CR * 128; i += 256)
            Hs[i] = h[(base + Sc + (i >> 7)) * 128 + (i & 127)];
        __syncthreads();

        for (int tt = tid; tt < CR * 32; tt += 256) {
            int r = tt >> 5;
            int col = (tt & 31) * 4;
            float4 acc = make_float4(0.f, 0.f, 0.f, 0.f);
#pragma unroll 4
            for (int k = 0; k < 128; k++) {
                float a = Hs[r * 128 + k];
                float4 b = *(const float4*)&Uf[k * 128 + col];
                acc.x += a * b.x; acc.y += a * b.y;
                acc.z += a * b.z; acc.w += a * b.w;
            }
            int gc = base + Sc + r;
            int gp = base + Sp + (r >> 1);
            float4 wf = *(const float4*)&g_wxf[gp * 128 + col];
            float4 cc = *(const float4*)&g_c[gc * 128 + col];
            float4 fc;
            fc.x = sigf(acc.x + wf.x) * cc.x;
            fc.y = sigf(acc.y + wf.y) * cc.y;
            fc.z = sigf(acc.z + wf.z) * cc.z;
            fc.w = sigf(acc.w + wf.w) * cc.w;
            *(float4*)&FC[r * 128 + col] = fc;
        }
        __syncthreads();

        for (int tt = tid; tt < P * 32; tt += 256) {
            int r = tt >> 5;
            int col = (tt & 31) * 4;
            float4 a0 = make_float4(0.f, 0.f, 0.f, 0.f);
            float4 a1 = a0, a2 = a0;
#pragma unroll 4
            for (int k = 0; k < 128; k++) {
                float a = Hs[(2 * r) * 128 + k] + Hs[(2 * r + 1) * 128 + k];
                float4 b0 = *(const float4*)&Uiou[k * D3 + col];
                float4 b1 = *(const float4*)&Uiou[k * D3 + 128 + col];
                float4 b2 = *(const float4*)&Uiou[k * D3 + 256 + col];
                a0.x += a * b0.x; a0.y += a * b0.y; a0.z += a * b0.z; a0.w += a * b0.w;
                a1.x += a * b1.x; a1.y += a * b1.y; a1.z += a * b1.z; a1.w += a * b1.w;
                a2.x += a * b2.x; a2.y += a * b2.y; a2.z += a * b2.z; a2.w += a * b2.w;
            }
            int gp = base + Sp + r;
            float4 w0 = *(const float4*)&g_wxiou[gp * D3 + col];
            float4 w1 = *(const float4*)&g_wxiou[gp * D3 + 128 + col];
            float4 w2 = *(const float4*)&g_wxiou[gp * D3 + 256 + col];
            float4 f1 = *(const float4*)&FC[(2 * r) * 128 + col];
            float4 f2 = *(const float4*)&FC[(2 * r + 1) * 128 + col];
            float4 cres, hres;
            {
                float cn = sigf(a0.x + w0.x) * tanhfast(a2.x + w2.x) + f1.x + f2.x;
                cres.x = cn; hres.x = sigf(a1.x + w1.x) * tanhfast(cn);
            }
            {
                float cn = sigf(a0.y + w0.y) * tanhfast(a2.y + w2.y) + f1.y + f2.y;
                cres.y = cn; hres.y = sigf(a1.y + w1.y) * tanhfast(cn);
            }
            {
                float cn = sigf(a0.z + w0.z) * tanhfast(a2.z + w2.z) + f1.z + f2.z;
                cres.z = cn; hres.z = sigf(a1.z + w1.z) * tanhfast(cn);
            }
            {
                float cn = sigf(a0.w + w0.w) * tanhfast(a2.w + w2.w) + f1.w + f2.w;
                cres.w = cn; hres.w = sigf(a1.w + w1.w) * tanhfast(cn);
            }
            *(float4*)&g_c[gp * 128 + col] = cres;
            *(float4*)&h[gp * 128 + col] = hres;
        }
        __syncthreads();
    }
}

// ---------------------------------------------------------------------------
extern "C" void kernel_launch(void* const* d_in, const int* in_sizes, int n_in,
                              void* d_out, int out_size)
{
    const float* features = (const float*)d_in[0];
    const float* W_iou    = (const float*)d_in[1];
    const float* b_iou    = (const float*)d_in[2];
    const float* U_iou    = (const float*)d_in[3];
    const float* W_f      = (const float*)d_in[4];
    const float* b_f      = (const float*)d_in[5];
    const float* U_f      = (const float*)d_in[6];
    float* h = (float*)d_out;

    (void)cudaFuncSetAttribute(k_wxiou, cudaFuncAttributeMaxDynamicSharedMemorySize, MM_SMEM);
    (void)cudaFuncSetAttribute(k_g128<0>, cudaFuncAttributeMaxDynamicSharedMemorySize, G128_SMEM);
    (void)cudaFuncSetAttribute(k_g128<1>, cudaFuncAttributeMaxDynamicSharedMemorySize, G128_SMEM);
    (void)cudaFuncSetAttribute(k_iou, cudaFuncAttributeMaxDynamicSharedMemorySize, IOU_SMEM);

    // Split weights to bf16 hi/lo, transposed
    k_cvt<<<192, 256>>>(W_iou, U_iou, W_f, U_f);

    // Level-independent GEMMs
    k_wxiou<<<dim3(1024, 6), 128, MM_SMEM>>>(features, b_iou);
    k_g128<0><<<512, 256, G128_SMEM>>>(features, b_f, 0);

    // Leaves (vectorized)
    k_leaf<<<4096, 256>>>(h);

    // Levels dd = 9..5: F kernel + IOU kernel
    for (int dd = 9; dd >= 5; dd--) {
        k_g128<1><<<(NT << (dd + 1)) / 64, 256, G128_SMEM>>>(h, nullptr, dd + 1);
        k_iou<<<(NT << dd) / 32, 256, IOU_SMEM>>>(h, dd);
    }

    // Tail: levels 4..0
    k_tail<<<32, 256>>>(h, U_f, U_iou);
}

// round 8
// speedup vs baseline: 1.2770x; 1.1953x over previous
#include <cuda_runtime.h>
#include <cuda_bf16.h>
#include <cstdint>

#define D3 384
#define MT 2047          // nodes per tree
#define NT 32
#define NN 65504         // 32 * 2047
#define NINT 32736       // 32 * 1023 internal nodes
#define SA 136           // smem row stride in bf16 (272B) -> ldmatrix conflict-free

// ------------------------- device scratch ----------------------------------
__device__ float g_wxiou[NN * D3];      // W_iou*x + b_iou (internal nodes used)
__device__ float g_wxf[NN * 128];       // W_f*x + b_f, internal nodes
__device__ float g_c[NN * 128];         // cell state
__device__ float g_fc[NN * 128];        // f(child)*c(child)
__device__ unsigned g_counts[32];       // global barrier slots (reset by k_leaf)

__device__ __align__(16) __nv_bfloat16 g_Wiou_h[D3 * 128];
__device__ __align__(16) __nv_bfloat16 g_Wiou_l[D3 * 128];
__device__ __align__(16) __nv_bfloat16 g_Uiou_h[D3 * 128];
__device__ __align__(16) __nv_bfloat16 g_Uiou_l[D3 * 128];
__device__ __align__(16) __nv_bfloat16 g_Wf_h[128 * 128];
__device__ __align__(16) __nv_bfloat16 g_Wf_l[128 * 128];
__device__ __align__(16) __nv_bfloat16 g_Uf_h[128 * 128];
__device__ __align__(16) __nv_bfloat16 g_Uf_l[128 * 128];

__device__ __forceinline__ float sigf(float x) {
    return 1.0f / (1.0f + __expf(-x));
}
__device__ __forceinline__ float tanhfast(float x) {
    return 1.0f - 2.0f / (__expf(2.0f * x) + 1.0f);
}

// ------------------------- mma / ldmatrix helpers ---------------------------
__device__ __forceinline__ void ldsm4(uint32_t addr, uint32_t* r) {
    asm volatile("ldmatrix.sync.aligned.m8n8.x4.shared.b16 {%0,%1,%2,%3}, [%4];"
                 : "=r"(r[0]), "=r"(r[1]), "=r"(r[2]), "=r"(r[3]) : "r"(addr));
}
__device__ __forceinline__ void mma16816(float* c, const uint32_t* a,
                                         uint32_t b0, uint32_t b1) {
    asm volatile(
        "mma.sync.aligned.m16n8k16.row.col.f32.bf16.bf16.f32 "
        "{%0,%1,%2,%3}, {%4,%5,%6,%7}, {%8,%9}, {%0,%1,%2,%3};"
        : "+f"(c[0]), "+f"(c[1]), "+f"(c[2]), "+f"(c[3])
        : "r"(a[0]), "r"(a[1]), "r"(a[2]), "r"(a[3]), "r"(b0), "r"(b1));
}
__device__ __forceinline__ void split1(float v, __nv_bfloat16& h, __nv_bfloat16& l) {
    h = __float2bfloat16(v);
    l = __float2bfloat16(v - __bfloat162float(h));
}
__device__ __forceinline__ void split_store4(float4 v, __nv_bfloat16* dh,
                                             __nv_bfloat16* dl) {
    __nv_bfloat16 h0, h1, h2, h3, l0, l1, l2, l3;
    split1(v.x, h0, l0); split1(v.y, h1, l1);
    split1(v.z, h2, l2); split1(v.w, h3, l3);
    __nv_bfloat162 p;
    p.x = h0; p.y = h1; ((__nv_bfloat162*)dh)[0] = p;
    p.x = h2; p.y = h3; ((__nv_bfloat162*)dh)[1] = p;
    p.x = l0; p.y = l1; ((__nv_bfloat162*)dl)[0] = p;
    p.x = l2; p.y = l3; ((__nv_bfloat162*)dl)[1] = p;
}

// ------------------------- weight split kernel ------------------------------
__global__ void k_cvt(const float* __restrict__ Wiou, const float* __restrict__ Uiou,
                      const float* __restrict__ Wf, const float* __restrict__ Uf)
{
    int idx = blockIdx.x * 256 + threadIdx.x;     // 384*128
    int n = idx >> 7, k = idx & 127;
    split1(Wiou[k * D3 + n], g_Wiou_h[n * 128 + k], g_Wiou_l[n * 128 + k]);
    split1(Uiou[k * D3 + n], g_Uiou_h[n * 128 + k], g_Uiou_l[n * 128 + k]);
    if (n < 128) {
        split1(Wf[k * 128 + n], g_Wf_h[n * 128 + k], g_Wf_l[n * 128 + k]);
        split1(Uf[k * 128 + n], g_Uf_h[n * 128 + k], g_Uf_l[n * 128 + k]);
    }
}

// ------------------------- wxiou precompute GEMM ----------------------------
#define MM_SMEM (4 * 64 * SA * 2)
__global__ __launch_bounds__(128) void k_wxiou(const float* __restrict__ Asrc,
                                               const float* __restrict__ bias)
{
    extern __shared__ __nv_bfloat16 sm[];
    __nv_bfloat16* As_h = sm;
    __nv_bfloat16* As_l = sm + 64 * SA;
    __nv_bfloat16* Bs_h = sm + 2 * 64 * SA;

    const int tid = threadIdx.x;
    const int row0 = blockIdx.x * 64;
    const int nb = blockIdx.y;

    {
        const int n0 = nb * 64;
#pragma unroll
        for (int s = 0; s < 8; s++) {
            int j = tid + s * 128;
            int r = j >> 4, q = j & 15;
            *(uint4*)&Bs_h[r * SA + q * 8] =
                *(const uint4*)&g_Wiou_h[(n0 + r) * 128 + q * 8];
            *(uint4*)&Bs_h[64 * SA + r * SA + q * 8] =
                *(const uint4*)&g_Wiou_l[(n0 + r) * 128 + q * 8];
        }
    }
#pragma unroll
    for (int s = 0; s < 16; s++) {
        int j = tid + s * 128;
        int r = j >> 5, kq = j & 31;
        int L = row0 + r;
        int g = (L < NN) ? L : NN - 1;
        float4 v = *(const float4*)&Asrc[g * 128 + kq * 4];
        split_store4(v, &As_h[r * SA + kq * 4], &As_l[r * SA + kq * 4]);
    }
    __syncthreads();

    const int lane = tid & 31, wid = tid >> 5;
    const int wm = (wid & 1) * 32, wn = (wid >> 1) * 32;

    float acc[2][4][4];
#pragma unroll
    for (int i = 0; i < 2; i++)
#pragma unroll
        for (int j = 0; j < 4; j++)
#pragma unroll
            for (int k = 0; k < 4; k++) acc[i][j][k] = 0.0f;

    const uint32_t smbase = (uint32_t)__cvta_generic_to_shared(sm);
    const uint32_t offAl = 64 * SA * 2;
    const uint32_t offBh = 2 * 64 * SA * 2;
    const uint32_t offBl = 3 * 64 * SA * 2;

    const int rA = lane & 15;
    const int kA8 = (lane >> 4) * 8;
    uint32_t adA0 = smbase + ((wm + rA) * SA + kA8) * 2;
    uint32_t adA1 = smbase + ((wm + 16 + rA) * SA + kA8) * 2;
    const int rB = (lane & 7) + ((lane >> 4) * 8);
    const int kB8 = ((lane >> 3) & 1) * 8;
    uint32_t adB0 = smbase + offBh + ((wn + rB) * SA + kB8) * 2;
    uint32_t adB1 = smbase + offBh + ((wn + 16 + rB) * SA + kB8) * 2;

#pragma unroll
    for (int kc = 0; kc < 8; kc++) {
        const uint32_t ko = kc * 32;
        uint32_t a_h[2][4], a_l[2][4], b_h[2][4], b_l[2][4];
        ldsm4(adA0 + ko, a_h[0]);
        ldsm4(adA1 + ko, a_h[1]);
        ldsm4(adA0 + offAl + ko, a_l[0]);
        ldsm4(adA1 + offAl + ko, a_l[1]);
        ldsm4(adB0 + ko, b_h[0]);
        ldsm4(adB1 + ko, b_h[1]);
        ldsm4(adB0 + (offBl - offBh) + ko, b_l[0]);
        ldsm4(adB1 + (offBl - offBh) + ko, b_l[1]);
#pragma unroll
        for (int mi = 0; mi < 2; mi++)
#pragma unroll
            for (int nt = 0; nt < 4; nt++) {
                uint32_t bh0 = b_h[nt >> 1][(nt & 1) * 2];
                uint32_t bh1 = b_h[nt >> 1][(nt & 1) * 2 + 1];
                uint32_t bl0 = b_l[nt >> 1][(nt & 1) * 2];
                uint32_t bl1 = b_l[nt >> 1][(nt & 1) * 2 + 1];
                mma16816(acc[mi][nt], a_h[mi], bh0, bh1);
                mma16816(acc[mi][nt], a_l[mi], bh0, bh1);
                mma16816(acc[mi][nt], a_h[mi], bl0, bl1);
            }
    }

    const int er = lane >> 2;
    const int ec = (lane & 3) * 2;
#pragma unroll
    for (int mi = 0; mi < 2; mi++)
#pragma unroll
        for (int nt = 0; nt < 4; nt++) {
            int n = nb * 64 + wn + nt * 8 + ec;
#pragma unroll
            for (int half = 0; half < 2; half++) {
                int L = row0 + wm + mi * 16 + er + half * 8;
                if (L < NN) {
                    float2 o;
                    o.x = acc[mi][nt][half * 2 + 0] + bias[n];
                    o.y = acc[mi][nt][half * 2 + 1] + bias[n + 1];
                    *(float2*)&g_wxiou[L * D3 + n] = o;
                }
            }
        }
}

// ------------------------- wxf precompute GEMM (N=128 resident) -------------
#define G128_SMEM ((2 * 64 + 2 * 128) * SA * 2)
__global__ __launch_bounds__(256) void k_wxf(const float* __restrict__ Asrc,
                                             const float* __restrict__ bias)
{
    extern __shared__ __nv_bfloat16 sm[];
    __nv_bfloat16* As_h = sm;
    __nv_bfloat16* As_l = sm + 64 * SA;
    __nv_bfloat16* Bs_h = sm + 2 * 64 * SA;
    __nv_bfloat16* Bs_l = sm + (2 * 64 + 128) * SA;

    const int tid = threadIdx.x;
    const int L0 = blockIdx.x * 64;

#pragma unroll
    for (int s = 0; s < 8; s++) {
        int j = tid + s * 256;
        int r = j >> 4, q = j & 15;
        *(uint4*)&Bs_h[r * SA + q * 8] = *(const uint4*)&g_Wf_h[r * 128 + q * 8];
        *(uint4*)&Bs_l[r * SA + q * 8] = *(const uint4*)&g_Wf_l[r * 128 + q * 8];
    }
#pragma unroll
    for (int s = 0; s < 8; s++) {
        int j = tid + s * 256;
        int r = j >> 5, kq = j & 31;
        int L = L0 + r;
        int Lc = (L < NINT) ? L : NINT - 1;
        int t = Lc / 1023;
        int g = t * MT + (Lc - t * 1023);
        float4 v = *(const float4*)&Asrc[g * 128 + kq * 4];
        split_store4(v, &As_h[r * SA + kq * 4], &As_l[r * SA + kq * 4]);
    }
    __syncthreads();

    const int lane = tid & 31, wid = tid >> 5;
    const int wm = (wid & 1) * 32, wn = (wid >> 1) * 32;

    float acc[2][4][4];
#pragma unroll
    for (int i = 0; i < 2; i++)
#pragma unroll
        for (int j = 0; j < 4; j++)
#pragma unroll
            for (int k = 0; k < 4; k++) acc[i][j][k] = 0.0f;

    const uint32_t smbase = (uint32_t)__cvta_generic_to_shared(sm);
    const uint32_t offAl = 64 * SA * 2;
    const uint32_t offBh = 2 * 64 * SA * 2;
    const uint32_t offBl = (2 * 64 + 128) * SA * 2;

    const int rA = lane & 15;
    const int kA8 = (lane >> 4) * 8;
    uint32_t adA0 = smbase + ((wm + rA) * SA + kA8) * 2;
    uint32_t adA1 = smbase + ((wm + 16 + rA) * SA + kA8) * 2;
    const int rB = (lane & 7) + ((lane >> 4) * 8);
    const int kB8 = ((lane >> 3) & 1) * 8;
    uint32_t adB0 = smbase + offBh + ((wn + rB) * SA + kB8) * 2;
    uint32_t adB1 = smbase + offBh + ((wn + 16 + rB) * SA + kB8) * 2;

#pragma unroll
    for (int kc = 0; kc < 8; kc++) {
        const uint32_t ko = kc * 32;
        uint32_t a_h[2][4], a_l[2][4], b_h[2][4], b_l[2][4];
        ldsm4(adA0 + ko, a_h[0]);
        ldsm4(adA1 + ko, a_h[1]);
        ldsm4(adA0 + offAl + ko, a_l[0]);
        ldsm4(adA1 + offAl + ko, a_l[1]);
        ldsm4(adB0 + ko, b_h[0]);
        ldsm4(adB1 + ko, b_h[1]);
        ldsm4(adB0 + (offBl - offBh) + ko, b_l[0]);
        ldsm4(adB1 + (offBl - offBh) + ko, b_l[1]);
#pragma unroll
        for (int mi = 0; mi < 2; mi++)
#pragma unroll
            for (int nt = 0; nt < 4; nt++) {
                uint32_t bh0 = b_h[nt >> 1][(nt & 1) * 2];
                uint32_t bh1 = b_h[nt >> 1][(nt & 1) * 2 + 1];
                uint32_t bl0 = b_l[nt >> 1][(nt & 1) * 2];
                uint32_t bl1 = b_l[nt >> 1][(nt & 1) * 2 + 1];
                mma16816(acc[mi][nt], a_h[mi], bh0, bh1);
                mma16816(acc[mi][nt], a_l[mi], bh0, bh1);
                mma16816(acc[mi][nt], a_h[mi], bl0, bl1);
            }
    }

    const int er = lane >> 2;
    const int ec = (lane & 3) * 2;
#pragma unroll
    for (int mi = 0; mi < 2; mi++)
#pragma unroll
        for (int nt = 0; nt < 4; nt++) {
            int n = wn + nt * 8 + ec;
#pragma unroll
            for (int half = 0; half < 2; half++) {
                int L = L0 + wm + mi * 16 + er + half * 8;
                if (L < NINT) {
                    int t = L / 1023;
                    int g = t * MT + (L - t * 1023);
                    float2 o;
                    o.x = acc[mi][nt][half * 2 + 0] + bias[n];
                    o.y = acc[mi][nt][half * 2 + 1] + bias[n + 1];
                    *(float2*)&g_wxf[g * 128 + n] = o;
                }
            }
        }
}

// ------------------------- leaf pass (also resets barriers) -----------------
__global__ void k_leaf(float* __restrict__ h)
{
    if (blockIdx.x == 0 && threadIdx.x < 32) g_counts[threadIdx.x] = 0;
    int idx = blockIdx.x * 256 + threadIdx.x;   // 32768 * 32 float4-cols
    int lr = idx >> 5, c4 = (idx & 31) * 4;
    int t = lr >> 10, r = lr & 1023;
    int g = t * MT + 1023 + r;
    float4 wi = *(const float4*)&g_wxiou[g * D3 + c4];
    float4 wo = *(const float4*)&g_wxiou[g * D3 + 128 + c4];
    float4 wu = *(const float4*)&g_wxiou[g * D3 + 256 + c4];
    float4 cres, hres;
    {
        float cn = sigf(wi.x) * tanhfast(wu.x);
        cres.x = cn; hres.x = sigf(wo.x) * tanhfast(cn);
    }
    {
        float cn = sigf(wi.y) * tanhfast(wu.y);
        cres.y = cn; hres.y = sigf(wo.y) * tanhfast(cn);
    }
    {
        float cn = sigf(wi.z) * tanhfast(wu.z);
        cres.z = cn; hres.z = sigf(wo.z) * tanhfast(cn);
    }
    {
        float cn = sigf(wi.w) * tanhfast(wu.w);
        cres.w = cn; hres.w = sigf(wo.w) * tanhfast(cn);
    }
    *(float4*)&g_c[g * 128 + c4] = cres;
    *(float4*)&h[g * 128 + c4] = hres;
}

// ------------------------- persistent level kernel --------------------------
// All levels dd=9..0 in ONE launch. Per level: F phase (64-child units,
// Uf resident) -> gbar -> IOU phase (32-parent units, Uiou 3x128 chunks,
// full cell update in epilogue) -> gbar.
#define LV_SMEM (384 * SA * 2)   // As_h(64) As_l(64) Bs_h(128) Bs_l(128)

__device__ __forceinline__ void gbar(int slot, int G) {
    __syncthreads();
    if (threadIdx.x == 0) {
        __threadfence();
        atomicAdd(&g_counts[slot], 1u);
        while (atomicAdd(&g_counts[slot], 0u) < (unsigned)G) __nanosleep(64);
        __threadfence();
    }
    __syncthreads();
}

__global__ __launch_bounds__(256, 2) void k_levels(float* __restrict__ h, int G)
{
    extern __shared__ __nv_bfloat16 sm[];
    __nv_bfloat16* As_h = sm;
    __nv_bfloat16* As_l = sm + 64 * SA;
    __nv_bfloat16* Bs_h = sm + 128 * SA;
    __nv_bfloat16* Bs_l = sm + 256 * SA;

    const int tid = threadIdx.x, lane = tid & 31, wid = tid >> 5;
    const int bid = blockIdx.x;
    const uint32_t smbase = (uint32_t)__cvta_generic_to_shared(sm);
    const uint32_t offAl = 64 * SA * 2;
    const uint32_t offBh = 128 * SA * 2;
    const uint32_t offBl = 256 * SA * 2;

    const int rA = lane & 15;
    const int kA8 = (lane >> 4) * 8;
    const int rB = (lane & 7) + ((lane >> 4) * 8);
    const int kB8 = ((lane >> 3) & 1) * 8;
    const int er = lane >> 2;
    const int ec = (lane & 3) * 2;

    int slot = 0;

    for (int dd = 9; dd >= 0; dd--) {
        const int cs = dd + 1;
        const int CH = 1 << cs;
        const int nU = 1 << dd;

        // ================= F phase: 64-child units =================
        if (bid < nU) {
            // Uf hi/lo resident for this level
            for (int j = tid; j < 128 * 16; j += 256) {
                int r = j >> 4, q = j & 15;
                *(uint4*)&Bs_h[r * SA + q * 8] = *(const uint4*)&g_Uf_h[r * 128 + q * 8];
                *(uint4*)&Bs_l[r * SA + q * 8] = *(const uint4*)&g_Uf_l[r * 128 + q * 8];
            }
            const int wm = (wid & 1) * 32, wn = (wid >> 1) * 32;
            uint32_t adA0 = smbase + ((wm + rA) * SA + kA8) * 2;
            uint32_t adA1 = smbase + ((wm + 16 + rA) * SA + kA8) * 2;
            uint32_t adB0 = smbase + offBh + ((wn + rB) * SA + kB8) * 2;
            uint32_t adB1 = smbase + offBh + ((wn + 16 + rB) * SA + kB8) * 2;

            for (int u = bid; u < nU; u += G) {
                const int L0 = u * 64;
                __syncthreads();
#pragma unroll
                for (int s = 0; s < 8; s++) {
                    int j = tid + s * 256;
                    int r = j >> 5, kq = j & 31;
                    int L = L0 + r;
                    int t = L >> cs, rr = L & (CH - 1);
                    int gc = t * MT + (CH - 1) + rr;
                    float4 v = *(const float4*)&h[gc * 128 + kq * 4];
                    split_store4(v, &As_h[r * SA + kq * 4], &As_l[r * SA + kq * 4]);
                }
                __syncthreads();

                float acc[2][4][4];
#pragma unroll
                for (int i = 0; i < 2; i++)
#pragma unroll
                    for (int j = 0; j < 4; j++)
#pragma unroll
                        for (int k = 0; k < 4; k++) acc[i][j][k] = 0.0f;

#pragma unroll
                for (int kc = 0; kc < 8; kc++) {
                    const uint32_t ko = kc * 32;
                    uint32_t a_h[2][4], a_l[2][4], b_h[2][4], b_l[2][4];
                    ldsm4(adA0 + ko, a_h[0]);
                    ldsm4(adA1 + ko, a_h[1]);
                    ldsm4(adA0 + offAl + ko, a_l[0]);
                    ldsm4(adA1 + offAl + ko, a_l[1]);
                    ldsm4(adB0 + ko, b_h[0]);
                    ldsm4(adB1 + ko, b_h[1]);
                    ldsm4(adB0 + (offBl - offBh) + ko, b_l[0]);
                    ldsm4(adB1 + (offBl - offBh) + ko, b_l[1]);
#pragma unroll
                    for (int mi = 0; mi < 2; mi++)
#pragma unroll
                        for (int nt = 0; nt < 4; nt++) {
                            uint32_t bh0 = b_h[nt >> 1][(nt & 1) * 2];
                            uint32_t bh1 = b_h[nt >> 1][(nt & 1) * 2 + 1];
                            uint32_t bl0 = b_l[nt >> 1][(nt & 1) * 2];
                            uint32_t bl1 = b_l[nt >> 1][(nt & 1) * 2 + 1];
                            mma16816(acc[mi][nt], a_h[mi], bh0, bh1);
                            mma16816(acc[mi][nt], a_l[mi], bh0, bh1);
                            mma16816(acc[mi][nt], a_h[mi], bl0, bl1);
                        }
                }
                // epilogue: g_fc = sig(acc + wxf[parent]) * c[child]
#pragma unroll
                for (int mi = 0; mi < 2; mi++)
#pragma unroll
                    for (int nt = 0; nt < 4; nt++) {
                        int n = wn + nt * 8 + ec;
#pragma unroll
                        for (int half = 0; half < 2; half++) {
                            int lr = wm + mi * 16 + er + half * 8;
                            int L = L0 + lr;
                            int t = L >> cs, rr = L & (CH - 1);
                            int gc = t * MT + (CH - 1) + rr;
                            int gp = t * MT + ((CH >> 1) - 1) + (rr >> 1);
                            float2 wf = *(const float2*)&g_wxf[gp * 128 + n];
                            float2 cc = *(const float2*)&g_c[gc * 128 + n];
                            float2 o;
                            o.x = sigf(acc[mi][nt][half * 2 + 0] + wf.x) * cc.x;
                            o.y = sigf(acc[mi][nt][half * 2 + 1] + wf.y) * cc.y;
                            *(float2*)&g_fc[gc * 128 + n] = o;
                        }
                    }
            }
        }
        gbar(slot++, G);

        // ================= IOU phase: 32-parent units =================
        if (bid < nU) {
            const int P = 1 << dd;
            const int wm = (wid & 1) * 16;     // 2 m-groups of 16 rows
            const int wn = (wid >> 1) * 32;    // 4 n-groups of 32 cols
            uint32_t adA = smbase + ((wm + rA) * SA + kA8) * 2;
            uint32_t adB0 = smbase + offBh + ((wn + rB) * SA + kB8) * 2;
            uint32_t adB1 = smbase + offBh + ((wn + 16 + rB) * SA + kB8) * 2;

            for (int u = bid; u < nU; u += G) {
                const int L0 = u * 32;
                __syncthreads();
#pragma unroll
                for (int s = 0; s < 4; s++) {
                    int j = tid + s * 256;
                    int r = j >> 5, kq = j & 31;
                    int L = L0 + r;
                    int t = L >> dd, rr = L & (P - 1);
                    int gc1 = t * MT + 2 * P - 1 + 2 * rr;
                    float4 v1 = *(const float4*)&h[gc1 * 128 + kq * 4];
                    float4 v2 = *(const float4*)&h[(gc1 + 1) * 128 + kq * 4];
                    float4 v = make_float4(v1.x + v2.x, v1.y + v2.y,
                                           v1.z + v2.z, v1.w + v2.w);
                    split_store4(v, &As_h[r * SA + kq * 4], &As_l[r * SA + kq * 4]);
                }

                float acc[3][4][4];
#pragma unroll
                for (int s = 0; s < 3; s++)
#pragma unroll
                    for (int j = 0; j < 4; j++)
#pragma unroll
                        for (int k = 0; k < 4; k++) acc[s][j][k] = 0.0f;

                for (int s3 = 0; s3 < 3; s3++) {
                    __syncthreads();
                    for (int j = tid; j < 128 * 16; j += 256) {
                        int r = j >> 4, q = j & 15;
                        *(uint4*)&Bs_h[r * SA + q * 8] =
                            *(const uint4*)&g_Uiou_h[(s3 * 128 + r) * 128 + q * 8];
                        *(uint4*)&Bs_l[r * SA + q * 8] =
                            *(const uint4*)&g_Uiou_l[(s3 * 128 + r) * 128 + q * 8];
                    }
                    __syncthreads();
#pragma unroll
                    for (int kc = 0; kc < 8; kc++) {
                        const uint32_t ko = kc * 32;
                        uint32_t a_h[4], a_l[4], b_h[2][4], b_l[2][4];
                        ldsm4(adA + ko, a_h);
                        ldsm4(adA + offAl + ko, a_l);
                        ldsm4(adB0 + ko, b_h[0]);
                        ldsm4(adB1 + ko, b_h[1]);
                        ldsm4(adB0 + (offBl - offBh) + ko, b_l[0]);
                        ldsm4(adB1 + (offBl - offBh) + ko, b_l[1]);
#pragma unroll
                        for (int nt = 0; nt < 4; nt++) {
                            uint32_t bh0 = b_h[nt >> 1][(nt & 1) * 2];
                            uint32_t bh1 = b_h[nt >> 1][(nt & 1) * 2 + 1];
                            uint32_t bl0 = b_l[nt >> 1][(nt & 1) * 2];
                            uint32_t bl1 = b_l[nt >> 1][(nt & 1) * 2 + 1];
                            mma16816(acc[s3][nt], a_h, bh0, bh1);
                            mma16816(acc[s3][nt], a_l, bh0, bh1);
                            mma16816(acc[s3][nt], a_h, bl0, bl1);
                        }
                    }
                }
                // epilogue: full cell update in registers
#pragma unroll
                for (int nt = 0; nt < 4; nt++) {
                    int col = wn + nt * 8 + ec;
#pragma unroll
                    for (int half = 0; half < 2; half++) {
                        int pr = wm + er + half * 8;
                        int L = L0 + pr;
                        int t = L >> dd, rr = L & (P - 1);
                        int gp = t * MT + P - 1 + rr;
                        int gc1 = t * MT + 2 * P - 1 + 2 * rr;
                        float2 wi = *(const float2*)&g_wxiou[gp * D3 + col];
                        float2 wo = *(const float2*)&g_wxiou[gp * D3 + 128 + col];
                        float2 wu = *(const float2*)&g_wxiou[gp * D3 + 256 + col];
                        float2 f1 = *(const float2*)&g_fc[gc1 * 128 + col];
                        float2 f2 = *(const float2*)&g_fc[(gc1 + 1) * 128 + col];
                        float2 cres, hres;
                        {
                            float cn = sigf(acc[0][nt][half * 2] + wi.x)
                                     * tanhfast(acc[2][nt][half * 2] + wu.x)
                                     + f1.x + f2.x;
                            cres.x = cn;
                            hres.x = sigf(acc[1][nt][half * 2] + wo.x) * tanhfast(cn);
                        }
                        {
                            float cn = sigf(acc[0][nt][half * 2 + 1] + wi.y)
                                     * tanhfast(acc[2][nt][half * 2 + 1] + wu.y)
                                     + f1.y + f2.y;
                            cres.y = cn;
                            hres.y = sigf(acc[1][nt][half * 2 + 1] + wo.y) * tanhfast(cn);
                        }
                        *(float2*)&g_c[gp * 128 + col] = cres;
                        *(float2*)&h[gp * 128 + col] = hres;
                    }
                }
            }
        }
        if (dd > 0) gbar(slot++, G);
    }
}

// ---------------------------------------------------------------------------
extern "C" void kernel_launch(void* const* d_in, const int* in_sizes, int n_in,
                              void* d_out, int out_size)
{
    const float* features = (const float*)d_in[0];
    const float* W_iou    = (const float*)d_in[1];
    const float* b_iou    = (const float*)d_in[2];
    const float* U_iou    = (const float*)d_in[3];
    const float* W_f      = (const float*)d_in[4];
    const float* b_f      = (const float*)d_in[5];
    const float* U_f      = (const float*)d_in[6];
    float* h = (float*)d_out;

    (void)cudaFuncSetAttribute(k_wxiou, cudaFuncAttributeMaxDynamicSharedMemorySize, MM_SMEM);
    (void)cudaFuncSetAttribute(k_wxf, cudaFuncAttributeMaxDynamicSharedMemorySize, G128_SMEM);
    (void)cudaFuncSetAttribute(k_levels, cudaFuncAttributeMaxDynamicSharedMemorySize, LV_SMEM);

    // Deadlock-proof persistent grid: occupancy x SM count (host queries only)
    int nsm = 148, occ = 1;
    (void)cudaDeviceGetAttribute(&nsm, cudaDevAttrMultiProcessorCount, 0);
    (void)cudaOccupancyMaxActiveBlocksPerMultiprocessor(&occ, k_levels, 256, LV_SMEM);
    if (occ < 1) occ = 1;
    if (occ > 2) occ = 2;
    int G = nsm * occ;

    k_cvt<<<192, 256>>>(W_iou, U_iou, W_f, U_f);
    k_wxiou<<<dim3(1024, 6), 128, MM_SMEM>>>(features, b_iou);
    k_wxf<<<512, 256, G128_SMEM>>>(features, b_f);
    k_leaf<<<4096, 256>>>(h);                 // also resets g_counts
    k_levels<<<G, 256, LV_SMEM>>>(h, G);
}